// round 13
// baseline (speedup 1.0000x reference)
#include <cuda_runtime.h>
#include <cuda_bf16.h>

// Scratch (no dynamic allocation allowed). B = 8192 here; headroom.
#define MAX_ROWS 16384
__device__ float g_row_loss[MAX_ROWS];
__device__ int   g_is_i64;   // 1 if y_true is int64-layout, 0 if int32

// ---------------------------------------------------------------------------
// Kernel 0: probe y_true dtype. If the first up-to-64 int64 interpretations
// are all in [0, C), the buffer is int64; a packed-int32 buffer fails this
// with probability ~(1/C)^64 ~ 0. All reads stay in bounds for either dtype.
// ---------------------------------------------------------------------------
__global__ void detect_label_dtype_kernel(const void* __restrict__ y_true,
                                          int B, int C, int* __restrict__ flag)
{
    const long long* p64 = (const long long*)y_true;
    int n = B / 2; if (n > 64) n = 64; if (n < 1) n = 1;
    int ok = 1;
    for (int i = 0; i < n; i++) {
        long long v = p64[i];
        if (v < 0 || v >= (long long)C) { ok = 0; break; }
    }
    *flag = ok;
}

// ---------------------------------------------------------------------------
// Kernel 1: one CTA per row. S = sum_c exp(y[b,c]) via streaming float4
// loads, then loss_b = log1p((S - exp(y_t)) * exp(-y_t)).
// ---------------------------------------------------------------------------
template <int BLOCK>
__global__ __launch_bounds__(BLOCK) void sup_contrastive_row_kernel(
    const float* __restrict__ y_pred,
    const void*  __restrict__ y_true,
    const int*   __restrict__ is_i64,
    float* __restrict__ row_loss,
    int C)
{
    const int b = blockIdx.x;
    const float* row = y_pred + (size_t)b * (size_t)C;

    // 4 independent accumulators to break the FADD dependency chain.
    float s0 = 0.f, s1 = 0.f, s2 = 0.f, s3 = 0.f;

    const int n4 = C >> 2;           // C = 32000 -> 8000 float4, 16B aligned
    const float4* row4 = reinterpret_cast<const float4*>(row);

    #pragma unroll 4
    for (int i = threadIdx.x; i < n4; i += BLOCK) {
        float4 v = __ldcs(&row4[i]);   // streaming: data read exactly once
        s0 += __expf(v.x);
        s1 += __expf(v.y);
        s2 += __expf(v.z);
        s3 += __expf(v.w);
    }
    // Scalar tail (no-op for C = 32000).
    for (int i = (n4 << 2) + threadIdx.x; i < C; i += BLOCK) {
        s0 += __expf(__ldcs(&row[i]));
    }

    float s = (s0 + s1) + (s2 + s3);

    // Warp reduce
    #pragma unroll
    for (int off = 16; off > 0; off >>= 1)
        s += __shfl_down_sync(0xFFFFFFFFu, s, off);

    __shared__ float warp_sums[BLOCK / 32];
    const int lane = threadIdx.x & 31;
    const int wid  = threadIdx.x >> 5;
    if (lane == 0) warp_sums[wid] = s;
    __syncthreads();

    if (wid == 0) {
        s = (lane < BLOCK / 32) ? warp_sums[lane] : 0.f;
        #pragma unroll
        for (int off = (BLOCK / 64); off > 0; off >>= 1)
            s += __shfl_down_sync(0xFFFFFFFFu, s, off);

        if (lane == 0) {
            int t;
            if (*is_i64) t = (int)((const long long*)y_true)[b];
            else         t = ((const int*)y_true)[b];
            // Defensive clamp: a wrong dtype guess must not fault.
            if (t < 0) t = 0; if (t >= C) t = C - 1;

            const float yt = row[t];
            const float et = __expf(yt);
            // negatives sum = S - exp(y_t); positive factor = exp(-y_t)
            row_loss[b] = log1pf((s - et) * __expf(-yt));
        }
    }
}

// ---------------------------------------------------------------------------
// Kernel 2: deterministic single-block mean over the per-row losses.
// ---------------------------------------------------------------------------
template <int BLOCK>
__global__ __launch_bounds__(BLOCK) void sup_contrastive_reduce_kernel(
    const float* __restrict__ row_loss,
    float* __restrict__ out,
    int B)
{
    float s = 0.f;
    for (int i = threadIdx.x; i < B; i += BLOCK)
        s += row_loss[i];

    #pragma unroll
    for (int off = 16; off > 0; off >>= 1)
        s += __shfl_down_sync(0xFFFFFFFFu, s, off);

    __shared__ float warp_sums[BLOCK / 32];
    const int lane = threadIdx.x & 31;
    const int wid  = threadIdx.x >> 5;
    if (lane == 0) warp_sums[wid] = s;
    __syncthreads();

    if (wid == 0) {
        s = (lane < BLOCK / 32) ? warp_sums[lane] : 0.f;
        #pragma unroll
        for (int off = (BLOCK / 64); off > 0; off >>= 1)
            s += __shfl_down_sync(0xFFFFFFFFu, s, off);
        if (lane == 0)
            out[0] = s / (float)B;
    }
}

// ---------------------------------------------------------------------------
// Entry point. y_pred identified as the LARGER input (robust to metadata
// ordering). Output: single fp32 scalar.
// ---------------------------------------------------------------------------
extern "C" void kernel_launch(void* const* d_in, const int* in_sizes, int n_in,
                              void* d_out, int out_size)
{
    const int i_pred = (in_sizes[0] >= in_sizes[1]) ? 0 : 1;
    const int i_true = 1 - i_pred;

    const float* y_pred = (const float*)d_in[i_pred];
    const void*  y_true = d_in[i_true];
    float* out = (float*)d_out;

    const int B = in_sizes[i_true];
    const int C = in_sizes[i_pred] / B;

    // One-time symbol lookups (pure address queries; capture-safe, no alloc).
    static float* row_loss = nullptr;
    static int*   is_i64   = nullptr;
    if (row_loss == nullptr) {
        cudaGetSymbolAddress((void**)&row_loss, g_row_loss);
        cudaGetSymbolAddress((void**)&is_i64,   g_is_i64);
    }

    constexpr int BLOCK = 256;
    detect_label_dtype_kernel<<<1, 1>>>(y_true, B, C, is_i64);
    sup_contrastive_row_kernel<BLOCK><<<B, BLOCK>>>(y_pred, y_true, is_i64, row_loss, C);
    sup_contrastive_reduce_kernel<BLOCK><<<1, BLOCK>>>(row_loss, out, B);
}

// round 15
// speedup vs baseline: 1.0196x; 1.0196x over previous
#include <cuda_runtime.h>
#include <cuda_bf16.h>

// Scratch (no dynamic allocation allowed). B = 8192 here; headroom.
#define MAX_ROWS 16384
__device__ float g_row_loss[MAX_ROWS];

// ---------------------------------------------------------------------------
// Kernel 1: one CTA per row. S = sum_c exp(y[b,c]) via streaming float4
// loads, then loss_b = log1p((S - exp(y_t)) * exp(-y_t)).
//
// Label dtype (int64 vs int32 layout) is detected inline by warp 0 in the
// epilogue: lanes check the first up-to-64 int64 interpretations against
// [0, C). A packed-int32 buffer passes that test with prob ~(1/C)^64 ~ 0.
// The probed bytes (<=512 B) are in bounds under either dtype and L2-hot
// after the first CTA touches them.
// ---------------------------------------------------------------------------
template <int BLOCK>
__global__ __launch_bounds__(BLOCK) void sup_contrastive_row_kernel(
    const float* __restrict__ y_pred,
    const void*  __restrict__ y_true,
    float* __restrict__ row_loss,
    int C)
{
    const int b = blockIdx.x;
    const float* row = y_pred + (size_t)b * (size_t)C;

    // 4 independent accumulators to break the FADD dependency chain.
    float s0 = 0.f, s1 = 0.f, s2 = 0.f, s3 = 0.f;

    const int n4 = C >> 2;           // C = 32000 -> 8000 float4, 16B aligned
    const float4* row4 = reinterpret_cast<const float4*>(row);

    #pragma unroll 8
    for (int i = threadIdx.x; i < n4; i += BLOCK) {
        float4 v = __ldcs(&row4[i]);   // streaming: data read exactly once
        s0 += __expf(v.x);
        s1 += __expf(v.y);
        s2 += __expf(v.z);
        s3 += __expf(v.w);
    }
    // Scalar tail (no-op for C = 32000).
    for (int i = (n4 << 2) + threadIdx.x; i < C; i += BLOCK) {
        s0 += __expf(__ldcs(&row[i]));
    }

    float s = (s0 + s1) + (s2 + s3);

    // Warp reduce
    #pragma unroll
    for (int off = 16; off > 0; off >>= 1)
        s += __shfl_down_sync(0xFFFFFFFFu, s, off);

    __shared__ float warp_sums[BLOCK / 32];
    const int lane = threadIdx.x & 31;
    const int wid  = threadIdx.x >> 5;
    if (lane == 0) warp_sums[wid] = s;
    __syncthreads();

    if (wid == 0) {
        s = (lane < BLOCK / 32) ? warp_sums[lane] : 0.f;
        #pragma unroll
        for (int off = (BLOCK / 64); off > 0; off >>= 1)
            s += __shfl_down_sync(0xFFFFFFFFu, s, off);

        // ---- inline dtype probe (whole warp, ballot) ----
        const int B = gridDim.x;
        const int n64 = max(1, min(64, B >> 1));
        const long long* p64 = (const long long*)y_true;
        int bad = 0;
        #pragma unroll
        for (int j = lane; j < 64; j += 32) {
            if (j < n64) {
                long long v = p64[j];
                if (v < 0 || v >= (long long)C) bad = 1;
            }
        }
        const int is64 = (__ballot_sync(0xFFFFFFFFu, bad) == 0u);

        if (lane == 0) {
            int t = is64 ? (int)p64[b] : ((const int*)y_true)[b];
            // Defensive clamp: a wrong dtype guess must not fault.
            if (t < 0) t = 0; if (t >= C) t = C - 1;

            const float yt = row[t];
            const float et = __expf(yt);
            // negatives sum = S - exp(y_t); positive factor = exp(-y_t)
            row_loss[b] = log1pf((s - et) * __expf(-yt));
        }
    }
}

// ---------------------------------------------------------------------------
// Kernel 2: deterministic single-block mean over the per-row losses.
// Vectorized float4 loads (B is a multiple of 4 here; scalar tail kept).
// ---------------------------------------------------------------------------
template <int BLOCK>
__global__ __launch_bounds__(BLOCK) void sup_contrastive_reduce_kernel(
    const float* __restrict__ row_loss,
    float* __restrict__ out,
    int B)
{
    float s = 0.f;
    const int n4 = B >> 2;
    const float4* rl4 = reinterpret_cast<const float4*>(row_loss);
    for (int i = threadIdx.x; i < n4; i += BLOCK) {
        float4 v = rl4[i];
        s += (v.x + v.y) + (v.z + v.w);
    }
    for (int i = (n4 << 2) + threadIdx.x; i < B; i += BLOCK)
        s += row_loss[i];

    #pragma unroll
    for (int off = 16; off > 0; off >>= 1)
        s += __shfl_down_sync(0xFFFFFFFFu, s, off);

    __shared__ float warp_sums[BLOCK / 32];
    const int lane = threadIdx.x & 31;
    const int wid  = threadIdx.x >> 5;
    if (lane == 0) warp_sums[wid] = s;
    __syncthreads();

    if (wid == 0) {
        s = (lane < BLOCK / 32) ? warp_sums[lane] : 0.f;
        #pragma unroll
        for (int off = (BLOCK / 64); off > 0; off >>= 1)
            s += __shfl_down_sync(0xFFFFFFFFu, s, off);
        if (lane == 0)
            out[0] = s / (float)B;
    }
}

// ---------------------------------------------------------------------------
// Entry point. y_pred identified as the LARGER input (robust to metadata
// ordering). Output: single fp32 scalar.
// ---------------------------------------------------------------------------
extern "C" void kernel_launch(void* const* d_in, const int* in_sizes, int n_in,
                              void* d_out, int out_size)
{
    const int i_pred = (in_sizes[0] >= in_sizes[1]) ? 0 : 1;
    const int i_true = 1 - i_pred;

    const float* y_pred = (const float*)d_in[i_pred];
    const void*  y_true = d_in[i_true];
    float* out = (float*)d_out;

    const int B = in_sizes[i_true];
    const int C = in_sizes[i_pred] / B;

    // One-time symbol lookup (pure address query; capture-safe, no alloc).
    static float* row_loss = nullptr;
    if (row_loss == nullptr)
        cudaGetSymbolAddress((void**)&row_loss, g_row_loss);

    constexpr int BLOCK = 256;
    sup_contrastive_row_kernel<BLOCK><<<B, BLOCK>>>(y_pred, y_true, row_loss, C);
    sup_contrastive_reduce_kernel<512><<<1, 512>>>(row_loss, out, B);
}